// round 4
// baseline (speedup 1.0000x reference)
#include <cuda_runtime.h>
#include <cuda_bf16.h>
#include <cstdint>

// ---------------- problem constants ----------------
#define BB     256
#define LMAXV  512
#define NC     300   // NCOND (K of GEMM1)
#define NH     600   // NHID  (N of GEMM1)
#define KPAD   320   // K padded to 10*32
#define NPAD   640   // N padded to 5*128

// ---------------- device scratch (no runtime allocs allowed) ----------------
__device__ float         g_pool[BB * NH];            // pooled SUMS (pre-division)
__device__ __nv_bfloat16 g_w1t_hi[NPAD * KPAD];      // W1^T split, [n][k]
__device__ __nv_bfloat16 g_w1t_lo[NPAD * KPAD];
__device__ __nv_bfloat16 g_ctx_hi[(size_t)BB * LMAXV * KPAD];  // ctx split, [b][l][k]
__device__ __nv_bfloat16 g_ctx_lo[(size_t)BB * LMAXV * KPAD];

// ---------------- helpers ----------------
__device__ __forceinline__ uint32_t s2u(const void* p) {
    uint32_t a;
    asm("{ .reg .u64 t; cvta.to.shared.u64 t, %1; cvt.u32.u64 %0, t; }" : "=r"(a) : "l"(p));
    return a;
}

__device__ __forceinline__ void cp16(uint32_t s, const void* g) {
    asm volatile("cp.async.cg.shared.global [%0], [%1], 16;" :: "r"(s), "l"(g));
}

__device__ __forceinline__ void ldm_x4(uint32_t* r, uint32_t addr) {
    asm volatile("ldmatrix.sync.aligned.m8n8.x4.shared.b16 {%0,%1,%2,%3}, [%4];"
                 : "=r"(r[0]), "=r"(r[1]), "=r"(r[2]), "=r"(r[3]) : "r"(addr));
}

__device__ __forceinline__ void mma_bf16(float* d, const uint32_t* a, const uint32_t* b) {
    asm volatile(
        "mma.sync.aligned.m16n8k16.row.col.f32.bf16.bf16.f32 "
        "{%0,%1,%2,%3}, {%4,%5,%6,%7}, {%8,%9}, {%0,%1,%2,%3};"
        : "+f"(d[0]), "+f"(d[1]), "+f"(d[2]), "+f"(d[3])
        : "r"(a[0]), "r"(a[1]), "r"(a[2]), "r"(a[3]), "r"(b[0]), "r"(b[1]));
}

// ---------------- prep: W1 -> W1^T hi/lo bf16, zero pooled sums ----------------
__global__ void prep_kernel(const float* __restrict__ W1) {
    int idx = blockIdx.x * blockDim.x + threadIdx.x;
    if (idx < NPAD * KPAD) {
        int n = idx / KPAD, k = idx % KPAD;
        float v = (n < NH && k < NC) ? W1[(size_t)k * NH + n] : 0.0f;
        __nv_bfloat16 hi = __float2bfloat16(v);
        g_w1t_hi[idx] = hi;
        g_w1t_lo[idx] = __float2bfloat16(v - __bfloat162float(hi));
    }
    if (idx < BB * NH) g_pool[idx] = 0.0f;
}

// ---------------- conv: ctx fp32 -> bf16 hi/lo, KPAD layout, valid tiles only ----
// grid = (4, 256), 512 threads. Converts ceil(len/128)*128 rows per batch.
__global__ __launch_bounds__(512)
void conv_kernel(const float* __restrict__ ctx, const int* __restrict__ lengths) {
    const int mt = blockIdx.x, b = blockIdx.y;
    int len = lengths[b]; if (len < 1) len = 1;
    if (mt * 128 >= len) return;

    const size_t in_row0  = ((size_t)b * LMAXV + (size_t)mt * 128) * NC;
    const size_t out_row0 = ((size_t)b * LMAXV + (size_t)mt * 128) * KPAD;

    // 128 rows x 80 float4-slots (k4 = 0..79; k4 >= 75 is zero padding)
    for (int idx = threadIdx.x; idx < 128 * 80; idx += 512) {
        int row = idx / 80, k4 = idx % 80;
        uint2 hi = make_uint2(0u, 0u), lo = make_uint2(0u, 0u);
        if (k4 < 75) {
            float4 v = *(const float4*)(ctx + in_row0 + (size_t)row * NC + k4 * 4);
            __nv_bfloat162 h01 = __floats2bfloat162_rn(v.x, v.y);
            __nv_bfloat162 h23 = __floats2bfloat162_rn(v.z, v.w);
            float2 f01 = __bfloat1622float2(h01);
            float2 f23 = __bfloat1622float2(h23);
            __nv_bfloat162 l01 = __floats2bfloat162_rn(v.x - f01.x, v.y - f01.y);
            __nv_bfloat162 l23 = __floats2bfloat162_rn(v.z - f23.x, v.w - f23.y);
            hi = make_uint2(*(uint32_t*)&h01, *(uint32_t*)&h23);
            lo = make_uint2(*(uint32_t*)&l01, *(uint32_t*)&l23);
        }
        size_t o = out_row0 + (size_t)row * KPAD + k4 * 4;
        *(uint2*)((__nv_bfloat16*)g_ctx_hi + o) = hi;
        *(uint2*)((__nv_bfloat16*)g_ctx_lo + o) = lo;
    }
}

// ---------------- Kernel A: double-buffered mma.sync GEMM1 + relu + masked pool ----
// grid = (nt=5, mt=4, b=256), 256 threads = 8 warps (4m x 2n), warp tile 32x64
// Dynamic SMEM: 2 stages x 4 tiles (Ahi,Alo,Bhi,Blo) x [128 rows x 80B]
#define TILE_B   (128 * 80)
#define STAGE_B  (4 * TILE_B)
#define SMEM_DYN (2 * STAGE_B)   // 81920

__global__ __launch_bounds__(256, 2)
void mma_pool_kernel(const int* __restrict__ lengths, const float* __restrict__ b1)
{
    extern __shared__ __align__(16) char dsm[];
    __shared__ float sbias[128];
    __shared__ float sred[128];

    const int nt = blockIdx.x, mt = blockIdx.y, b = blockIdx.z;
    int len = lengths[b]; if (len < 1) len = 1;
    if (mt * 128 >= len) return;

    const int tid  = threadIdx.x;
    const int warp = tid >> 5, lane = tid & 31;
    const int warp_m = (warp & 3) * 32;   // 4 warps along M
    const int warp_n = (warp >> 2) * 64;  // 2 warps along N

    const int n0 = nt * 128;
    const uint32_t sb = s2u(dsm);

    const __nv_bfloat16* gAhi = g_ctx_hi + ((size_t)b * LMAXV + (size_t)mt * 128) * KPAD;
    const __nv_bfloat16* gAlo = g_ctx_lo + ((size_t)b * LMAXV + (size_t)mt * 128) * KPAD;
    const __nv_bfloat16* gBhi = g_w1t_hi + (size_t)n0 * KPAD;
    const __nv_bfloat16* gBlo = g_w1t_lo + (size_t)n0 * KPAD;

    // staging map: per thread 2 (row,q) pairs per tile
    const int r0 = tid >> 2,         q0 = tid & 3;         // rows 0..63
    const int r1 = 64 + (tid >> 2);                        // rows 64..127

    if (tid < 128) {
        int j = n0 + tid;
        sbias[tid] = (j < NH) ? b1[j] : 0.0f;
        sred[tid] = 0.0f;
    }

    // ldmatrix per-lane offsets
    const int t = lane >> 3, r = lane & 7;
    const uint32_t aoff = (uint32_t)(((t & 1) * 8 + r) * 80 + (t >> 1) * 16);
    const uint32_t boff = (uint32_t)((((t >> 1) * 8) + r) * 80 + (t & 1) * 16);

    float acc[2][8][4];
    #pragma unroll
    for (int i = 0; i < 2; i++)
        #pragma unroll
        for (int j = 0; j < 8; j++)
            #pragma unroll
            for (int q = 0; q < 4; q++) acc[i][j][q] = 0.0f;

    auto stage = [&](int c, int s) {
        const uint32_t base = sb + s * STAGE_B;
        const int ke = c * 32 + q0 * 8;                    // element k offset
        const uint32_t d0 = (uint32_t)(r0 * 80 + q0 * 16);
        const uint32_t d1 = (uint32_t)(r1 * 80 + q0 * 16);
        cp16(base + 0 * TILE_B + d0, gAhi + (size_t)r0 * KPAD + ke);
        cp16(base + 0 * TILE_B + d1, gAhi + (size_t)r1 * KPAD + ke);
        cp16(base + 1 * TILE_B + d0, gAlo + (size_t)r0 * KPAD + ke);
        cp16(base + 1 * TILE_B + d1, gAlo + (size_t)r1 * KPAD + ke);
        cp16(base + 2 * TILE_B + d0, gBhi + (size_t)r0 * KPAD + ke);
        cp16(base + 2 * TILE_B + d1, gBhi + (size_t)r1 * KPAD + ke);
        cp16(base + 3 * TILE_B + d0, gBlo + (size_t)r0 * KPAD + ke);
        cp16(base + 3 * TILE_B + d1, gBlo + (size_t)r1 * KPAD + ke);
        asm volatile("cp.async.commit_group;" ::: "memory");
    };

    stage(0, 0);

    for (int c = 0; c < 10; c++) {
        const int s = c & 1;
        if (c + 1 < 10) {
            stage(c + 1, s ^ 1);
            asm volatile("cp.async.wait_group 1;" ::: "memory");
        } else {
            asm volatile("cp.async.wait_group 0;" ::: "memory");
        }
        __syncthreads();

        const uint32_t uA = sb + s * STAGE_B;
        const uint32_t uAhi = uA, uAlo = uA + TILE_B;
        const uint32_t uBhi = uA + 2 * TILE_B, uBlo = uA + 3 * TILE_B;

        #pragma unroll
        for (int ks = 0; ks < 2; ks++) {
            uint32_t ahi[2][4], alo[2][4];
            #pragma unroll
            for (int m2 = 0; m2 < 2; m2++) {
                uint32_t ab = (uint32_t)((warp_m + m2 * 16) * 80 + ks * 32);
                ldm_x4(ahi[m2], uAhi + ab + aoff);
                ldm_x4(alo[m2], uAlo + ab + aoff);
            }
            #pragma unroll
            for (int np = 0; np < 4; np++) {
                uint32_t bh[4], bl[4];
                uint32_t bb = (uint32_t)((warp_n + np * 16) * 80 + ks * 32);
                ldm_x4(bh, uBhi + bb + boff);
                ldm_x4(bl, uBlo + bb + boff);
                #pragma unroll
                for (int m2 = 0; m2 < 2; m2++) {
                    mma_bf16(acc[m2][2 * np],     ahi[m2], bh);
                    mma_bf16(acc[m2][2 * np + 1], ahi[m2], bh + 2);
                    mma_bf16(acc[m2][2 * np],     ahi[m2], bl);
                    mma_bf16(acc[m2][2 * np + 1], ahi[m2], bl + 2);
                    mma_bf16(acc[m2][2 * np],     alo[m2], bh);
                    mma_bf16(acc[m2][2 * np + 1], alo[m2], bh + 2);
                }
            }
        }
        __syncthreads();   // all reads of stage s done before it is re-staged
    }

    // ---- epilogue: bias + relu + row-mask + column sums ----
    const int lrow = lane >> 2;
    const int lcol = (lane & 3) * 2;
    const int gm_base = mt * 128 + warp_m;

    #pragma unroll
    for (int n8 = 0; n8 < 8; n8++) {
        int ncc = warp_n + n8 * 8 + lcol;
        float be = sbias[ncc], bo = sbias[ncc + 1];
        float se = 0.0f, so = 0.0f;
        #pragma unroll
        for (int m2 = 0; m2 < 2; m2++) {
            int row0 = gm_base + m2 * 16 + lrow;
            bool v0 = row0 < len;
            bool v1 = (row0 + 8) < len;
            const float* a = acc[m2][n8];
            if (v0) { se += fmaxf(a[0] + be, 0.0f); so += fmaxf(a[1] + bo, 0.0f); }
            if (v1) { se += fmaxf(a[2] + be, 0.0f); so += fmaxf(a[3] + bo, 0.0f); }
        }
        #pragma unroll
        for (int d = 4; d < 32; d <<= 1) {
            se += __shfl_xor_sync(0xffffffffu, se, d);
            so += __shfl_xor_sync(0xffffffffu, so, d);
        }
        if (lane < 4) {
            atomicAdd(&sred[ncc], se);
            atomicAdd(&sred[ncc + 1], so);
        }
    }
    __syncthreads();
    if (tid < 128) {
        int j = n0 + tid;
        if (j < NH) atomicAdd(&g_pool[(size_t)b * NH + j], sred[tid]);
    }
}

// ---------------- Kernel B: gate = sigmoid(pooled/len @ Wa + ba); out = gate * x ----
#define GB 2
__global__ __launch_bounds__(320)
void gate_kernel(const float* __restrict__ x,
                 const float* __restrict__ Wa,
                 const float* __restrict__ ba,
                 const int*   __restrict__ lengths,
                 float*       __restrict__ out)
{
    __shared__ float ps[GB][NH];
    const int b0 = blockIdx.x * GB, tid = threadIdx.x;

    float inv[GB];
    #pragma unroll
    for (int g = 0; g < GB; g++) {
        int len = lengths[b0 + g]; if (len < 1) len = 1;
        inv[g] = 1.0f / (float)len;
    }
    for (int i = tid; i < GB * NH; i += 320) {
        int g = i / NH, h = i % NH;
        ps[g][h] = g_pool[(size_t)(b0 + g) * NH + h] * inv[g];
    }
    __syncthreads();

    if (tid < NC) {
        float a0 = ba[tid], a1 = a0;
        #pragma unroll 8
        for (int h = 0; h < NH; h++) {
            float w = Wa[(size_t)h * NC + tid];
            a0 = fmaf(ps[0][h], w, a0);
            a1 = fmaf(ps[1][h], w, a1);
        }
        float g0 = 1.0f / (1.0f + expf(-a0));
        float g1 = 1.0f / (1.0f + expf(-a1));
        out[(size_t)b0 * NC + tid]       = g0 * x[(size_t)b0 * NC + tid];
        out[(size_t)(b0 + 1) * NC + tid] = g1 * x[(size_t)(b0 + 1) * NC + tid];
    }
}

// ---------------- launch ----------------
// metadata order: x, context, lengths, W1, b1, Wa, ba
extern "C" void kernel_launch(void* const* d_in, const int* in_sizes, int n_in,
                              void* d_out, int out_size)
{
    const float* x       = (const float*)d_in[0];
    const float* context = (const float*)d_in[1];
    const int*   lengths = (const int*)  d_in[2];
    const float* W1      = (const float*)d_in[3];
    const float* b1      = (const float*)d_in[4];
    const float* Wa      = (const float*)d_in[5];
    const float* ba      = (const float*)d_in[6];
    float* out = (float*)d_out;

    cudaFuncSetAttribute(mma_pool_kernel,
                         cudaFuncAttributeMaxDynamicSharedMemorySize, SMEM_DYN);

    prep_kernel<<<(NPAD * KPAD + 255) / 256, 256>>>(W1);

    dim3 gconv(4, BB);
    conv_kernel<<<gconv, 512>>>(context, lengths);

    dim3 grid(5, 4, BB);
    mma_pool_kernel<<<grid, 256, SMEM_DYN>>>(lengths, b1);

    gate_kernel<<<BB / GB, 320>>>(x, Wa, ba, lengths, out);
}

// round 5
// speedup vs baseline: 1.4754x; 1.4754x over previous
#include <cuda_runtime.h>
#include <cuda_fp16.h>
#include <cstdint>

// ---------------- problem constants ----------------
#define BB     256
#define LMAXV  512
#define NC     300   // NCOND (K of GEMM1)
#define NH     600   // NHID  (N of GEMM1)
#define KPAD   320   // K padded to 10*32
#define NPAD   640   // N padded to 5*128

// ---------------- device scratch (no runtime allocs allowed) ----------------
__device__ float  g_pool[BB * NH];                      // pooled SUMS (pre-division)
__device__ __half g_w1t[NPAD * KPAD];                   // W1^T fp16, [n][k]
__device__ __half g_ctx[(size_t)BB * LMAXV * KPAD];     // ctx fp16, [b][l][k]

// ---------------- helpers ----------------
__device__ __forceinline__ uint32_t s2u(const void* p) {
    uint32_t a;
    asm("{ .reg .u64 t; cvta.to.shared.u64 t, %1; cvt.u32.u64 %0, t; }" : "=r"(a) : "l"(p));
    return a;
}

__device__ __forceinline__ void cp16(uint32_t s, const void* g) {
    asm volatile("cp.async.cg.shared.global [%0], [%1], 16;" :: "r"(s), "l"(g));
}

__device__ __forceinline__ void ldm_x4(uint32_t* r, uint32_t addr) {
    asm volatile("ldmatrix.sync.aligned.m8n8.x4.shared.b16 {%0,%1,%2,%3}, [%4];"
                 : "=r"(r[0]), "=r"(r[1]), "=r"(r[2]), "=r"(r[3]) : "r"(addr));
}

__device__ __forceinline__ void mma_f16(float* d, const uint32_t* a, const uint32_t* b) {
    asm volatile(
        "mma.sync.aligned.m16n8k16.row.col.f32.f16.f16.f32 "
        "{%0,%1,%2,%3}, {%4,%5,%6,%7}, {%8,%9}, {%0,%1,%2,%3};"
        : "+f"(d[0]), "+f"(d[1]), "+f"(d[2]), "+f"(d[3])
        : "r"(a[0]), "r"(a[1]), "r"(a[2]), "r"(a[3]), "r"(b[0]), "r"(b[1]));
}

// ---------------- prep: W1 -> W1^T fp16, zero pooled sums ----------------
__global__ void prep_kernel(const float* __restrict__ W1) {
    int idx = blockIdx.x * blockDim.x + threadIdx.x;
    if (idx < NPAD * KPAD) {
        int n = idx / KPAD, k = idx % KPAD;
        float v = (n < NH && k < NC) ? W1[(size_t)k * NH + n] : 0.0f;
        g_w1t[idx] = __float2half_rn(v);
    }
    if (idx < BB * NH) g_pool[idx] = 0.0f;
}

// ---------------- conv: ctx fp32 -> fp16, KPAD layout, valid tiles only ----------
// grid = (4, 256), 512 threads. Converts ceil(len/128)*128 rows per batch.
__global__ __launch_bounds__(512)
void conv_kernel(const float* __restrict__ ctx, const int* __restrict__ lengths) {
    const int mt = blockIdx.x, b = blockIdx.y;
    int len = lengths[b]; if (len < 1) len = 1;
    if (mt * 128 >= len) return;

    const size_t in_row0  = ((size_t)b * LMAXV + (size_t)mt * 128) * NC;
    const size_t out_row0 = ((size_t)b * LMAXV + (size_t)mt * 128) * KPAD;

    // 128 rows x 80 groups of 4 elements (k4 >= 75 is zero padding)
    for (int idx = threadIdx.x; idx < 128 * 80; idx += 512) {
        int row = idx / 80, k4 = idx % 80;
        uint2 h = make_uint2(0u, 0u);
        if (k4 < 75) {
            float4 v = *(const float4*)(ctx + in_row0 + (size_t)row * NC + k4 * 4);
            __half2 h01 = __floats2half2_rn(v.x, v.y);
            __half2 h23 = __floats2half2_rn(v.z, v.w);
            h = make_uint2(*(uint32_t*)&h01, *(uint32_t*)&h23);
        }
        *(uint2*)((__half*)g_ctx + out_row0 + (size_t)row * KPAD + k4 * 4) = h;
    }
}

// ---------------- Kernel A: double-buffered fp16 mma GEMM1 + relu + masked pool ----
// grid = (nt=5, mt=4, b=256), 256 threads = 8 warps (4m x 2n), warp tile 32x64
// Dynamic SMEM: 2 stages x 2 tiles (A, B) x [128 rows x 80B]
#define TILE_B   (128 * 80)
#define STAGE_B  (2 * TILE_B)
#define SMEM_DYN (2 * STAGE_B)   // 40960

__global__ __launch_bounds__(256, 3)
void mma_pool_kernel(const int* __restrict__ lengths, const float* __restrict__ b1)
{
    extern __shared__ __align__(16) char dsm[];
    __shared__ float sbias[128];
    __shared__ float sred[128];

    const int nt = blockIdx.x, mt = blockIdx.y, b = blockIdx.z;
    int len = lengths[b]; if (len < 1) len = 1;
    if (mt * 128 >= len) return;

    const int tid  = threadIdx.x;
    const int warp = tid >> 5, lane = tid & 31;
    const int warp_m = (warp & 3) * 32;   // 4 warps along M
    const int warp_n = (warp >> 2) * 64;  // 2 warps along N

    const int n0 = nt * 128;
    const uint32_t sb = s2u(dsm);

    const __half* gA = g_ctx + ((size_t)b * LMAXV + (size_t)mt * 128) * KPAD;
    const __half* gB = g_w1t + (size_t)n0 * KPAD;

    // staging map: per thread 2 (row, q) pairs per tile
    const int r0 = tid >> 2, q0 = tid & 3;   // rows 0..63
    const int r1 = 64 + r0;                  // rows 64..127

    if (tid < 128) {
        int j = n0 + tid;
        sbias[tid] = (j < NH) ? b1[j] : 0.0f;
        sred[tid] = 0.0f;
    }

    // ldmatrix per-lane offsets
    const int t = lane >> 3, r = lane & 7;
    const uint32_t aoff = (uint32_t)(((t & 1) * 8 + r) * 80 + (t >> 1) * 16);
    const uint32_t boff = (uint32_t)((((t >> 1) * 8) + r) * 80 + (t & 1) * 16);

    float acc[2][8][4];
    #pragma unroll
    for (int i = 0; i < 2; i++)
        #pragma unroll
        for (int j = 0; j < 8; j++)
            #pragma unroll
            for (int q = 0; q < 4; q++) acc[i][j][q] = 0.0f;

    auto stage = [&](int c, int s) {
        const uint32_t base = sb + s * STAGE_B;
        const int ke = c * 32 + q0 * 8;                  // k element offset
        const uint32_t d0 = (uint32_t)(r0 * 80 + q0 * 16);
        const uint32_t d1 = (uint32_t)(r1 * 80 + q0 * 16);
        cp16(base + d0,          gA + (size_t)r0 * KPAD + ke);
        cp16(base + d1,          gA + (size_t)r1 * KPAD + ke);
        cp16(base + TILE_B + d0, gB + (size_t)r0 * KPAD + ke);
        cp16(base + TILE_B + d1, gB + (size_t)r1 * KPAD + ke);
        asm volatile("cp.async.commit_group;" ::: "memory");
    };

    stage(0, 0);

    for (int c = 0; c < 10; c++) {
        const int s = c & 1;
        if (c + 1 < 10) {
            stage(c + 1, s ^ 1);
            asm volatile("cp.async.wait_group 1;" ::: "memory");
        } else {
            asm volatile("cp.async.wait_group 0;" ::: "memory");
        }
        __syncthreads();

        const uint32_t uA = sb + s * STAGE_B;
        const uint32_t uB = uA + TILE_B;

        #pragma unroll
        for (int ks = 0; ks < 2; ks++) {
            uint32_t a[2][4];
            #pragma unroll
            for (int m2 = 0; m2 < 2; m2++)
                ldm_x4(a[m2], uA + (uint32_t)((warp_m + m2 * 16) * 80 + ks * 32) + aoff);
            #pragma unroll
            for (int np = 0; np < 4; np++) {
                uint32_t bf[4];
                ldm_x4(bf, uB + (uint32_t)((warp_n + np * 16) * 80 + ks * 32) + boff);
                #pragma unroll
                for (int m2 = 0; m2 < 2; m2++) {
                    mma_f16(acc[m2][2 * np],     a[m2], bf);
                    mma_f16(acc[m2][2 * np + 1], a[m2], bf + 2);
                }
            }
        }
        __syncthreads();   // all reads of stage s done before it is re-staged
    }

    // ---- epilogue: bias + relu + row-mask + column sums ----
    const int lrow = lane >> 2;
    const int lcol = (lane & 3) * 2;
    const int gm_base = mt * 128 + warp_m;

    #pragma unroll
    for (int n8 = 0; n8 < 8; n8++) {
        int ncc = warp_n + n8 * 8 + lcol;
        float be = sbias[ncc], bo = sbias[ncc + 1];
        float se = 0.0f, so = 0.0f;
        #pragma unroll
        for (int m2 = 0; m2 < 2; m2++) {
            int row0 = gm_base + m2 * 16 + lrow;
            bool v0 = row0 < len;
            bool v1 = (row0 + 8) < len;
            const float* a = acc[m2][n8];
            if (v0) { se += fmaxf(a[0] + be, 0.0f); so += fmaxf(a[1] + bo, 0.0f); }
            if (v1) { se += fmaxf(a[2] + be, 0.0f); so += fmaxf(a[3] + bo, 0.0f); }
        }
        #pragma unroll
        for (int d = 4; d < 32; d <<= 1) {
            se += __shfl_xor_sync(0xffffffffu, se, d);
            so += __shfl_xor_sync(0xffffffffu, so, d);
        }
        if (lane < 4) {
            atomicAdd(&sred[ncc], se);
            atomicAdd(&sred[ncc + 1], so);
        }
    }
    __syncthreads();
    if (tid < 128) {
        int j = n0 + tid;
        if (j < NH) atomicAdd(&g_pool[(size_t)b * NH + j], sred[tid]);
    }
}

// ---------------- Kernel B: gate = sigmoid(pooled/len @ Wa + ba); out = gate * x ----
// grid = 256 (one batch per block), 640 threads: NH reduction split 2-way.
__global__ __launch_bounds__(640)
void gate_kernel(const float* __restrict__ x,
                 const float* __restrict__ Wa,
                 const float* __restrict__ ba,
                 const int*   __restrict__ lengths,
                 float*       __restrict__ out)
{
    __shared__ float ps[NH];
    __shared__ float part[NC];
    const int b = blockIdx.x, tid = threadIdx.x;
    const int half = tid / 320, j = tid - half * 320;

    int len = lengths[b]; if (len < 1) len = 1;
    const float inv = 1.0f / (float)len;

    for (int i = tid; i < NH; i += 640)
        ps[i] = g_pool[(size_t)b * NH + i] * inv;
    __syncthreads();

    float a = 0.0f;
    if (j < NC) {
        const int h0 = half * 300;
        #pragma unroll 10
        for (int h = 0; h < 300; h++)
            a = fmaf(ps[h0 + h], Wa[(size_t)(h0 + h) * NC + j], a);
        if (half == 1) part[j] = a;
    }
    __syncthreads();
    if (half == 0 && j < NC) {
        float z = a + part[j] + ba[j];
        float g = 1.0f / (1.0f + expf(-z));
        out[(size_t)b * NC + j] = g * x[(size_t)b * NC + j];
    }
}

// ---------------- launch ----------------
// metadata order: x, context, lengths, W1, b1, Wa, ba
extern "C" void kernel_launch(void* const* d_in, const int* in_sizes, int n_in,
                              void* d_out, int out_size)
{
    const float* x       = (const float*)d_in[0];
    const float* context = (const float*)d_in[1];
    const int*   lengths = (const int*)  d_in[2];
    const float* W1      = (const float*)d_in[3];
    const float* b1      = (const float*)d_in[4];
    const float* Wa      = (const float*)d_in[5];
    const float* ba      = (const float*)d_in[6];
    float* out = (float*)d_out;

    cudaFuncSetAttribute(mma_pool_kernel,
                         cudaFuncAttributeMaxDynamicSharedMemorySize, SMEM_DYN);

    prep_kernel<<<(NPAD * KPAD + 255) / 256, 256>>>(W1);

    dim3 gconv(4, BB);
    conv_kernel<<<gconv, 512>>>(context, lengths);

    dim3 grid(5, 4, BB);
    mma_pool_kernel<<<grid, 256, SMEM_DYN>>>(lengths, b1);

    gate_kernel<<<BB, 640>>>(x, Wa, ba, lengths, out);
}

// round 6
// speedup vs baseline: 1.7811x; 1.2072x over previous
#include <cuda_runtime.h>
#include <cuda_fp16.h>
#include <cstdint>

// ---------------- problem constants ----------------
#define BB     256
#define LMAXV  512
#define NC     300   // NCOND (K of GEMM1)
#define NH     600   // NHID  (N of GEMM1)
#define KPAD   320   // K padded to 10*32
#define NPAD   640   // N padded to 5*128

// ---------------- device scratch (no runtime allocs allowed) ----------------
__device__ float  g_pool[BB * NH];                      // pooled SUMS (pre-division)
__device__ __half g_w1t[NPAD * KPAD];                   // W1^T fp16, [n][k]
__device__ __half g_ctx[(size_t)BB * LMAXV * KPAD];     // ctx fp16, [b][l][k]

// ---------------- helpers ----------------
__device__ __forceinline__ uint32_t s2u(const void* p) {
    uint32_t a;
    asm("{ .reg .u64 t; cvta.to.shared.u64 t, %1; cvt.u32.u64 %0, t; }" : "=r"(a) : "l"(p));
    return a;
}

__device__ __forceinline__ void cp16(uint32_t s, const void* g) {
    asm volatile("cp.async.cg.shared.global [%0], [%1], 16;" :: "r"(s), "l"(g));
}

__device__ __forceinline__ void ldm_x4(uint32_t* r, uint32_t addr) {
    asm volatile("ldmatrix.sync.aligned.m8n8.x4.shared.b16 {%0,%1,%2,%3}, [%4];"
                 : "=r"(r[0]), "=r"(r[1]), "=r"(r[2]), "=r"(r[3]) : "r"(addr));
}

__device__ __forceinline__ void mma_f16(float* d, const uint32_t* a, const uint32_t* b) {
    asm volatile(
        "mma.sync.aligned.m16n8k16.row.col.f32.f16.f16.f32 "
        "{%0,%1,%2,%3}, {%4,%5,%6,%7}, {%8,%9}, {%0,%1,%2,%3};"
        : "+f"(d[0]), "+f"(d[1]), "+f"(d[2]), "+f"(d[3])
        : "r"(a[0]), "r"(a[1]), "r"(a[2]), "r"(a[3]), "r"(b[0]), "r"(b[1]));
}

// ---------------- prep: W1 -> W1^T fp16, zero pooled sums ----------------
__global__ void prep_kernel(const float* __restrict__ W1) {
    int idx = blockIdx.x * blockDim.x + threadIdx.x;
    if (idx < NPAD * KPAD) {
        int n = idx / KPAD, k = idx % KPAD;
        float v = (n < NH && k < NC) ? W1[(size_t)k * NH + n] : 0.0f;
        g_w1t[idx] = __float2half_rn(v);
    }
    if (idx < BB * NH) g_pool[idx] = 0.0f;
}

// ---------------- conv: ctx fp32 -> fp16, KPAD layout, valid tiles only ----------
__global__ __launch_bounds__(512)
void conv_kernel(const float* __restrict__ ctx, const int* __restrict__ lengths) {
    const int mt = blockIdx.x, b = blockIdx.y;
    int len = lengths[b]; if (len < 1) len = 1;
    if (mt * 128 >= len) return;

    const size_t in_row0  = ((size_t)b * LMAXV + (size_t)mt * 128) * NC;
    const size_t out_row0 = ((size_t)b * LMAXV + (size_t)mt * 128) * KPAD;

    for (int idx = threadIdx.x; idx < 128 * 80; idx += 512) {
        int row = idx / 80, k4 = idx % 80;
        uint2 h = make_uint2(0u, 0u);
        if (k4 < 75) {
            float4 v = *(const float4*)(ctx + in_row0 + (size_t)row * NC + k4 * 4);
            __half2 h01 = __floats2half2_rn(v.x, v.y);
            __half2 h23 = __floats2half2_rn(v.z, v.w);
            h = make_uint2(*(uint32_t*)&h01, *(uint32_t*)&h23);
        }
        *(uint2*)((__half*)g_ctx + out_row0 + (size_t)row * KPAD + k4 * 4) = h;
    }
}

// ---------------- Kernel A: 3-stage cp.async fp16 mma GEMM1 + relu + masked pool ----
// grid = (nt=5, mt=4, b=256), 256 threads = 8 warps (4m x 2n), warp tile 32x64
// Dynamic SMEM: 3 stages x 2 tiles (A, B) x [128 rows x 80B]
#define TILE_B   (128 * 80)
#define STAGE_B  (2 * TILE_B)
#define SMEM_DYN (3 * STAGE_B)   // 61440

__global__ __launch_bounds__(256, 2)
void mma_pool_kernel(const int* __restrict__ lengths, const float* __restrict__ b1)
{
    extern __shared__ __align__(16) char dsm[];
    __shared__ float sbias[128];
    __shared__ float sred[128];

    const int nt = blockIdx.x, mt = blockIdx.y, b = blockIdx.z;
    int len = lengths[b]; if (len < 1) len = 1;
    if (mt * 128 >= len) return;

    const int tid  = threadIdx.x;
    const int warp = tid >> 5, lane = tid & 31;
    const int warp_m = (warp & 3) * 32;   // 4 warps along M
    const int warp_n = (warp >> 2) * 64;  // 2 warps along N

    const int n0 = nt * 128;
    const uint32_t sb = s2u(dsm);

    const __half* gA = g_ctx + ((size_t)b * LMAXV + (size_t)mt * 128) * KPAD;
    const __half* gB = g_w1t + (size_t)n0 * KPAD;

    // staging map: per thread 2 (row, q) pairs per tile
    const int r0 = tid >> 2, q0 = tid & 3;   // rows 0..63
    const int r1 = 64 + r0;                  // rows 64..127

    if (tid < 128) {
        int j = n0 + tid;
        sbias[tid] = (j < NH) ? b1[j] : 0.0f;
        sred[tid] = 0.0f;
    }

    // ldmatrix per-lane offsets
    const int t = lane >> 3, r = lane & 7;
    const uint32_t aoff = (uint32_t)(((t & 1) * 8 + r) * 80 + (t >> 1) * 16);
    const uint32_t boff = (uint32_t)((((t >> 1) * 8) + r) * 80 + (t & 1) * 16);

    float acc[2][8][4];
    #pragma unroll
    for (int i = 0; i < 2; i++)
        #pragma unroll
        for (int j = 0; j < 8; j++)
            #pragma unroll
            for (int q = 0; q < 4; q++) acc[i][j][q] = 0.0f;

    auto stage = [&](int c, int s) {
        const uint32_t base = sb + s * STAGE_B;
        const int ke = c * 32 + q0 * 8;                  // k element offset
        const uint32_t d0 = (uint32_t)(r0 * 80 + q0 * 16);
        const uint32_t d1 = (uint32_t)(r1 * 80 + q0 * 16);
        cp16(base + d0,          gA + (size_t)r0 * KPAD + ke);
        cp16(base + d1,          gA + (size_t)r1 * KPAD + ke);
        cp16(base + TILE_B + d0, gB + (size_t)r0 * KPAD + ke);
        cp16(base + TILE_B + d1, gB + (size_t)r1 * KPAD + ke);
        asm volatile("cp.async.commit_group;" ::: "memory");
    };

    stage(0, 0);
    stage(1, 1);

    for (int c = 0; c < 10; c++) {
        const int s = c - (c / 3) * 3;       // c % 3
        // ensure chunk c's group has landed (chunk c+1 may still be in flight)
        if (c + 1 < 10)
            asm volatile("cp.async.wait_group 1;" ::: "memory");
        else
            asm volatile("cp.async.wait_group 0;" ::: "memory");
        __syncthreads();   // also orders last iteration's reads before restaging below

        // prefetch chunk c+2 into buffer (c+2)%3 — last read two iterations ago
        if (c + 2 < 10) {
            int s2 = (c + 2) - ((c + 2) / 3) * 3;
            stage(c + 2, s2);
        }

        const uint32_t uA = sb + s * STAGE_B;
        const uint32_t uB = uA + TILE_B;

        #pragma unroll
        for (int ks = 0; ks < 2; ks++) {
            uint32_t a[2][4];
            #pragma unroll
            for (int m2 = 0; m2 < 2; m2++)
                ldm_x4(a[m2], uA + (uint32_t)((warp_m + m2 * 16) * 80 + ks * 32) + aoff);
            #pragma unroll
            for (int np = 0; np < 4; np++) {
                uint32_t bf[4];
                ldm_x4(bf, uB + (uint32_t)((warp_n + np * 16) * 80 + ks * 32) + boff);
                #pragma unroll
                for (int m2 = 0; m2 < 2; m2++) {
                    mma_f16(acc[m2][2 * np],     a[m2], bf);
                    mma_f16(acc[m2][2 * np + 1], a[m2], bf + 2);
                }
            }
        }
    }

    // ---- epilogue: bias + relu + row-mask + column sums ----
    __syncthreads();
    const int lrow = lane >> 2;
    const int lcol = (lane & 3) * 2;
    const int gm_base = mt * 128 + warp_m;

    #pragma unroll
    for (int n8 = 0; n8 < 8; n8++) {
        int ncc = warp_n + n8 * 8 + lcol;
        float be = sbias[ncc], bo = sbias[ncc + 1];
        float se = 0.0f, so = 0.0f;
        #pragma unroll
        for (int m2 = 0; m2 < 2; m2++) {
            int row0 = gm_base + m2 * 16 + lrow;
            bool v0 = row0 < len;
            bool v1 = (row0 + 8) < len;
            const float* a = acc[m2][n8];
            if (v0) { se += fmaxf(a[0] + be, 0.0f); so += fmaxf(a[1] + bo, 0.0f); }
            if (v1) { se += fmaxf(a[2] + be, 0.0f); so += fmaxf(a[3] + bo, 0.0f); }
        }
        #pragma unroll
        for (int d = 4; d < 32; d <<= 1) {
            se += __shfl_xor_sync(0xffffffffu, se, d);
            so += __shfl_xor_sync(0xffffffffu, so, d);
        }
        if (lane < 4) {
            atomicAdd(&sred[ncc], se);
            atomicAdd(&sred[ncc + 1], so);
        }
    }
    __syncthreads();
    if (tid < 128) {
        int j = n0 + tid;
        if (j < NH) atomicAdd(&g_pool[(size_t)b * NH + j], sred[tid]);
    }
}

// ---------------- Kernel B: gate = sigmoid(pooled/len @ Wa + ba); out = gate * x ----
// grid = 256 (one batch per block), 640 threads; NH split 2-way + 2-way ILP.
__global__ __launch_bounds__(640)
void gate_kernel(const float* __restrict__ x,
                 const float* __restrict__ Wa,
                 const float* __restrict__ ba,
                 const int*   __restrict__ lengths,
                 float*       __restrict__ out)
{
    __shared__ float ps[NH];
    __shared__ float part[NC];
    const int b = blockIdx.x, tid = threadIdx.x;
    const int half = tid / 320, j = tid - half * 320;

    int len = lengths[b]; if (len < 1) len = 1;
    const float inv = 1.0f / (float)len;

    for (int i = tid; i < NH; i += 640)
        ps[i] = g_pool[(size_t)b * NH + i] * inv;
    __syncthreads();

    float a0 = 0.0f, a1 = 0.0f;
    if (j < NC) {
        const int h0 = half * 300;
        #pragma unroll 10
        for (int h = 0; h < 300; h += 2) {
            a0 = fmaf(ps[h0 + h],     Wa[(size_t)(h0 + h)     * NC + j], a0);
            a1 = fmaf(ps[h0 + h + 1], Wa[(size_t)(h0 + h + 1) * NC + j], a1);
        }
        if (half == 1) part[j] = a0 + a1;
    }
    __syncthreads();
    if (half == 0 && j < NC) {
        float z = a0 + a1 + part[j] + ba[j];
        float g = 1.0f / (1.0f + expf(-z));
        out[(size_t)b * NC + j] = g * x[(size_t)b * NC + j];
    }
}

// ---------------- launch ----------------
// metadata order: x, context, lengths, W1, b1, Wa, ba
extern "C" void kernel_launch(void* const* d_in, const int* in_sizes, int n_in,
                              void* d_out, int out_size)
{
    const float* x       = (const float*)d_in[0];
    const float* context = (const float*)d_in[1];
    const int*   lengths = (const int*)  d_in[2];
    const float* W1      = (const float*)d_in[3];
    const float* b1      = (const float*)d_in[4];
    const float* Wa      = (const float*)d_in[5];
    const float* ba      = (const float*)d_in[6];
    float* out = (float*)d_out;

    cudaFuncSetAttribute(mma_pool_kernel,
                         cudaFuncAttributeMaxDynamicSharedMemorySize, SMEM_DYN);

    prep_kernel<<<(NPAD * KPAD + 255) / 256, 256>>>(W1);

    dim3 gconv(4, BB);
    conv_kernel<<<gconv, 512>>>(context, lengths);

    dim3 grid(5, 4, BB);
    mma_pool_kernel<<<grid, 256, SMEM_DYN>>>(lengths, b1);

    gate_kernel<<<BB, 640>>>(x, Wa, ba, lengths, out);
}

// round 7
// speedup vs baseline: 1.9407x; 1.0896x over previous
#include <cuda_runtime.h>
#include <cuda_fp16.h>
#include <cstdint>

// ---------------- problem constants ----------------
#define BB     256
#define LMAXV  512
#define NC     300   // NCOND (K of GEMM1)
#define NH     600   // NHID  (N of GEMM1)
#define KPAD   320   // K padded to 10*32 (only 300 real; 300..320 zeros)
#define NPAD   640   // N padded to 5*128

// ---------------- device scratch (no runtime allocs allowed) ----------------
__device__ float  g_pool[BB * NH];                      // pooled SUMS (pre-division)
__device__ float  g_gpart[4][BB * NC];                  // gate GEMM split-K partials
__device__ __half g_w1t[NPAD * KPAD];                   // W1^T fp16, [n][k]
__device__ __half g_ctx[(size_t)BB * LMAXV * KPAD];     // ctx fp16, [b][l][k]

// ---------------- helpers ----------------
__device__ __forceinline__ uint32_t s2u(const void* p) {
    uint32_t a;
    asm("{ .reg .u64 t; cvta.to.shared.u64 t, %1; cvt.u32.u64 %0, t; }" : "=r"(a) : "l"(p));
    return a;
}

__device__ __forceinline__ void cp16(uint32_t s, const void* g) {
    asm volatile("cp.async.cg.shared.global [%0], [%1], 16;" :: "r"(s), "l"(g));
}

__device__ __forceinline__ void ldm_x4(uint32_t* r, uint32_t addr) {
    asm volatile("ldmatrix.sync.aligned.m8n8.x4.shared.b16 {%0,%1,%2,%3}, [%4];"
                 : "=r"(r[0]), "=r"(r[1]), "=r"(r[2]), "=r"(r[3]) : "r"(addr));
}

__device__ __forceinline__ void mma_f16(float* d, const uint32_t* a, const uint32_t* b) {
    asm volatile(
        "mma.sync.aligned.m16n8k16.row.col.f32.f16.f16.f32 "
        "{%0,%1,%2,%3}, {%4,%5,%6,%7}, {%8,%9}, {%0,%1,%2,%3};"
        : "+f"(d[0]), "+f"(d[1]), "+f"(d[2]), "+f"(d[3])
        : "r"(a[0]), "r"(a[1]), "r"(a[2]), "r"(a[3]), "r"(b[0]), "r"(b[1]));
}

// ---------------- prep: W1 -> W1^T fp16, zero pooled sums ----------------
__global__ void prep_kernel(const float* __restrict__ W1) {
    int idx = blockIdx.x * blockDim.x + threadIdx.x;
    if (idx < NPAD * KPAD) {
        int n = idx / KPAD, k = idx % KPAD;
        float v = (n < NH && k < NC) ? W1[(size_t)k * NH + n] : 0.0f;
        g_w1t[idx] = __float2half_rn(v);
    }
    if (idx < BB * NH) g_pool[idx] = 0.0f;
}

// ---------------- conv: ctx fp32 -> fp16, KPAD layout, valid tiles only ----------
__global__ __launch_bounds__(512)
void conv_kernel(const float* __restrict__ ctx, const int* __restrict__ lengths) {
    const int mt = blockIdx.x, b = blockIdx.y;
    int len = lengths[b]; if (len < 1) len = 1;
    if (mt * 128 >= len) return;

    const size_t in_row0  = ((size_t)b * LMAXV + (size_t)mt * 128) * NC;
    const size_t out_row0 = ((size_t)b * LMAXV + (size_t)mt * 128) * KPAD;

    for (int idx = threadIdx.x; idx < 128 * 80; idx += 512) {
        int row = idx / 80, k4 = idx % 80;
        uint2 h = make_uint2(0u, 0u);
        if (k4 < 75) {
            float4 v = *(const float4*)(ctx + in_row0 + (size_t)row * NC + k4 * 4);
            __half2 h01 = __floats2half2_rn(v.x, v.y);
            __half2 h23 = __floats2half2_rn(v.z, v.w);
            h = make_uint2(*(uint32_t*)&h01, *(uint32_t*)&h23);
        }
        *(uint2*)((__half*)g_ctx + out_row0 + (size_t)row * KPAD + k4 * 4) = h;
    }
}

// ---------------- Kernel A: 3-stage cp.async fp16 mma GEMM1 + relu + masked pool ----
// grid = (nt=5, mt=4, b=256), 256 threads = 8 warps (4m x 2n), warp tile 32x64
#define TILE_B   (128 * 80)
#define STAGE_B  (2 * TILE_B)
#define SMEM_DYN (3 * STAGE_B)   // 61440

__global__ __launch_bounds__(256, 2)
void mma_pool_kernel(const int* __restrict__ lengths, const float* __restrict__ b1)
{
    extern __shared__ __align__(16) char dsm[];
    __shared__ float sbias[128];
    __shared__ float sred[128];

    const int nt = blockIdx.x, mt = blockIdx.y, b = blockIdx.z;
    int len = lengths[b]; if (len < 1) len = 1;
    if (mt * 128 >= len) return;

    const int tid  = threadIdx.x;
    const int warp = tid >> 5, lane = tid & 31;
    const int warp_m = (warp & 3) * 32;   // 4 warps along M
    const int warp_n = (warp >> 2) * 64;  // 2 warps along N

    const int n0 = nt * 128;
    const uint32_t sb = s2u(dsm);

    const __half* gA = g_ctx + ((size_t)b * LMAXV + (size_t)mt * 128) * KPAD;
    const __half* gB = g_w1t + (size_t)n0 * KPAD;

    const int r0 = tid >> 2, q0 = tid & 3;   // rows 0..63
    const int r1 = 64 + r0;                  // rows 64..127

    if (tid < 128) {
        int j = n0 + tid;
        sbias[tid] = (j < NH) ? b1[j] : 0.0f;
        sred[tid] = 0.0f;
    }

    const int t = lane >> 3, r = lane & 7;
    const uint32_t aoff = (uint32_t)(((t & 1) * 8 + r) * 80 + (t >> 1) * 16);
    const uint32_t boff = (uint32_t)((((t >> 1) * 8) + r) * 80 + (t & 1) * 16);

    float acc[2][8][4];
    #pragma unroll
    for (int i = 0; i < 2; i++)
        #pragma unroll
        for (int j = 0; j < 8; j++)
            #pragma unroll
            for (int q = 0; q < 4; q++) acc[i][j][q] = 0.0f;

    auto stage = [&](int c, int s) {
        const uint32_t base = sb + s * STAGE_B;
        const int ke = c * 32 + q0 * 8;
        const uint32_t d0 = (uint32_t)(r0 * 80 + q0 * 16);
        const uint32_t d1 = (uint32_t)(r1 * 80 + q0 * 16);
        cp16(base + d0,          gA + (size_t)r0 * KPAD + ke);
        cp16(base + d1,          gA + (size_t)r1 * KPAD + ke);
        cp16(base + TILE_B + d0, gB + (size_t)r0 * KPAD + ke);
        cp16(base + TILE_B + d1, gB + (size_t)r1 * KPAD + ke);
        asm volatile("cp.async.commit_group;" ::: "memory");
    };

    stage(0, 0);
    stage(1, 1);

    for (int c = 0; c < 10; c++) {
        const int s = c - (c / 3) * 3;       // c % 3
        if (c + 1 < 10)
            asm volatile("cp.async.wait_group 1;" ::: "memory");
        else
            asm volatile("cp.async.wait_group 0;" ::: "memory");
        __syncthreads();

        if (c + 2 < 10) {
            int s2 = (c + 2) - ((c + 2) / 3) * 3;
            stage(c + 2, s2);
        }

        const uint32_t uA = sb + s * STAGE_B;
        const uint32_t uB = uA + TILE_B;

        // ks=0 always; ks=1 skipped for chunk 9 (k=304..320 is all zero padding)
        const int nks = (c == 9) ? 1 : 2;
        for (int ks = 0; ks < nks; ks++) {
            uint32_t a[2][4];
            #pragma unroll
            for (int m2 = 0; m2 < 2; m2++)
                ldm_x4(a[m2], uA + (uint32_t)((warp_m + m2 * 16) * 80 + ks * 32) + aoff);
            #pragma unroll
            for (int np = 0; np < 4; np++) {
                uint32_t bf[4];
                ldm_x4(bf, uB + (uint32_t)((warp_n + np * 16) * 80 + ks * 32) + boff);
                #pragma unroll
                for (int m2 = 0; m2 < 2; m2++) {
                    mma_f16(acc[m2][2 * np],     a[m2], bf);
                    mma_f16(acc[m2][2 * np + 1], a[m2], bf + 2);
                }
            }
        }
    }

    // ---- epilogue: bias + relu + row-mask + column sums ----
    __syncthreads();
    const int lrow = lane >> 2;
    const int lcol = (lane & 3) * 2;
    const int gm_base = mt * 128 + warp_m;

    #pragma unroll
    for (int n8 = 0; n8 < 8; n8++) {
        int ncc = warp_n + n8 * 8 + lcol;
        float be = sbias[ncc], bo = sbias[ncc + 1];
        float se = 0.0f, so = 0.0f;
        #pragma unroll
        for (int m2 = 0; m2 < 2; m2++) {
            int row0 = gm_base + m2 * 16 + lrow;
            bool v0 = row0 < len;
            bool v1 = (row0 + 8) < len;
            const float* a = acc[m2][n8];
            if (v0) { se += fmaxf(a[0] + be, 0.0f); so += fmaxf(a[1] + bo, 0.0f); }
            if (v1) { se += fmaxf(a[2] + be, 0.0f); so += fmaxf(a[3] + bo, 0.0f); }
        }
        #pragma unroll
        for (int d = 4; d < 32; d <<= 1) {
            se += __shfl_xor_sync(0xffffffffu, se, d);
            so += __shfl_xor_sync(0xffffffffu, so, d);
        }
        if (lane < 4) {
            atomicAdd(&sred[ncc], se);
            atomicAdd(&sred[ncc + 1], so);
        }
    }
    __syncthreads();
    if (tid < 128) {
        int j = n0 + tid;
        if (j < NH) atomicAdd(&g_pool[(size_t)b * NH + j], sred[tid]);
    }
}

// ---------------- gate phase 1: split-K partials ----------------
// grid = (4 NH-quarters, 64 batch-groups), 320 threads; 4 batches per block
// share every Wa load across 4 independent accumulator chains.
__global__ __launch_bounds__(320)
void gate1_kernel(const float* __restrict__ Wa, const int* __restrict__ lengths)
{
    __shared__ float ps[4][152];
    const int q  = blockIdx.x;           // NH quarter
    const int b0 = blockIdx.y * 4;       // batch group
    const int tid = threadIdx.x;

    for (int i = tid; i < 4 * 150; i += 320) {
        int g = i / 150, h = i - g * 150;
        int len = lengths[b0 + g]; if (len < 1) len = 1;
        ps[g][h] = g_pool[(size_t)(b0 + g) * NH + q * 150 + h] / (float)len;
    }
    __syncthreads();

    const int j = tid;
    if (j < NC) {
        float a0 = 0.f, a1 = 0.f, a2 = 0.f, a3 = 0.f;
        const float* w = Wa + (size_t)q * 150 * NC + j;
        #pragma unroll 5
        for (int h = 0; h < 150; h++) {
            float wv = w[(size_t)h * NC];
            a0 = fmaf(ps[0][h], wv, a0);
            a1 = fmaf(ps[1][h], wv, a1);
            a2 = fmaf(ps[2][h], wv, a2);
            a3 = fmaf(ps[3][h], wv, a3);
        }
        float* gp = g_gpart[q];
        gp[(size_t)(b0 + 0) * NC + j] = a0;
        gp[(size_t)(b0 + 1) * NC + j] = a1;
        gp[(size_t)(b0 + 2) * NC + j] = a2;
        gp[(size_t)(b0 + 3) * NC + j] = a3;
    }
}

// ---------------- gate phase 2: sigmoid finisher ----------------
__global__ __launch_bounds__(256)
void gate2_kernel(const float* __restrict__ x,
                  const float* __restrict__ ba,
                  float*       __restrict__ out)
{
    int idx = blockIdx.x * 256 + threadIdx.x;
    if (idx < BB * NC) {
        int j = idx % NC;
        float z = ba[j] + g_gpart[0][idx] + g_gpart[1][idx]
                        + g_gpart[2][idx] + g_gpart[3][idx];
        float g = 1.0f / (1.0f + expf(-z));
        out[idx] = g * x[idx];
    }
}

// ---------------- launch ----------------
// metadata order: x, context, lengths, W1, b1, Wa, ba
extern "C" void kernel_launch(void* const* d_in, const int* in_sizes, int n_in,
                              void* d_out, int out_size)
{
    const float* x       = (const float*)d_in[0];
    const float* context = (const float*)d_in[1];
    const int*   lengths = (const int*)  d_in[2];
    const float* W1      = (const float*)d_in[3];
    const float* b1      = (const float*)d_in[4];
    const float* Wa      = (const float*)d_in[5];
    const float* ba      = (const float*)d_in[6];
    float* out = (float*)d_out;

    cudaFuncSetAttribute(mma_pool_kernel,
                         cudaFuncAttributeMaxDynamicSharedMemorySize, SMEM_DYN);

    prep_kernel<<<(NPAD * KPAD + 255) / 256, 256>>>(W1);

    dim3 gconv(4, BB);
    conv_kernel<<<gconv, 512>>>(context, lengths);

    dim3 grid(5, 4, BB);
    mma_pool_kernel<<<grid, 256, SMEM_DYN>>>(lengths, b1);

    dim3 g1(4, BB / 4);
    gate1_kernel<<<g1, 320>>>(Wa, lengths);

    gate2_kernel<<<(BB * NC + 255) / 256, 256>>>(x, ba, out);
}